// round 8
// baseline (speedup 1.0000x reference)
#include <cuda_runtime.h>
#include <math.h>

// Problem constants
#define B_  4
#define T_  2048
#define D_  512
#define H_  8
#define DK_ 64
#define BT_ (B_ * T_)

// ---------------- device scratch (no allocations allowed) ----------------
__device__ float g_sq[T_], g_sk[T_], g_sv[T_], g_sx[T_];       // per-token act scales
__device__ float g_wsq[D_], g_wsk[D_], g_wsv[D_];              // per-col weight scales
__device__ signed char g_aq[BT_ * D_], g_ak[BT_ * D_], g_av[BT_ * D_]; // int8 acts
__device__ signed char g_xq8[BT_ * D_];                         // int8 of attention out
__device__ signed char g_wtq[D_ * D_], g_wtk[D_ * D_], g_wtv[D_ * D_]; // int8 W^T [j][k]
__device__ float g_q[B_ * H_ * T_ * DK_];
__device__ float g_kk[B_ * H_ * T_ * DK_];
__device__ float g_kkT[B_ * H_ * DK_ * T_];   // K transposed: [bh][d][t]
__device__ float g_vv[B_ * H_ * T_ * DK_];
__device__ float g_x[BT_ * D_];

// ---- emulate XLA:GPU's f32 division (div.full.f32, <=2ulp) — ONLY for the
// bit-critical quantization divisions (rintf bin boundaries). ----
__device__ __forceinline__ float div_full(float a, float b) {
    float r;
    asm("div.full.f32 %0, %1, %2;" : "=f"(r) : "f"(a), "f"(b));
    return r;
}
__device__ __forceinline__ float make_scale(float absmax) {
    return fmaxf(div_full(absmax, 127.0f), 1e-8f);
}
__device__ __forceinline__ signed char quant_val(float v, float s) {
    float q = rintf(div_full(v, s));
    q = fminf(127.0f, fmaxf(-128.0f, q));
    return (signed char)(int)q;
}

// ---- packed f32x2 helpers (Blackwell) — each lane an independent fp32 acc ----
typedef unsigned long long ull;
__device__ __forceinline__ ull fma2(ull a, ull b, ull c) {
    ull d;
    asm("fma.rn.f32x2 %0, %1, %2, %3;" : "=l"(d) : "l"(a), "l"(b), "l"(c));
    return d;
}
__device__ __forceinline__ ull mul2(ull a, ull b) {
    ull d;
    asm("mul.rn.f32x2 %0, %1, %2;" : "=l"(d) : "l"(a), "l"(b));
    return d;
}
__device__ __forceinline__ ull dup2(float x) {
    ull d;
    asm("mov.b64 %0, {%1, %1};" : "=l"(d) : "f"(x));
    return d;
}
__device__ __forceinline__ float2 unpk(ull v) {
    float lo, hi;
    asm("mov.b64 {%0, %1}, %2;" : "=f"(lo), "=f"(hi) : "l"(v));
    return make_float2(lo, hi);
}

// ---------------- per-token activation scale + int8 quantize ------------------
__global__ void act_quant_kernel(const float* __restrict__ xq,
                                 const float* __restrict__ xk,
                                 const float* __restrict__ xv,
                                 int final_mode) {
    int t = blockIdx.x;
    const float* x;
    float* sptr;
    signed char* outq;
    if (final_mode) {
        x = g_x; sptr = g_sx; outq = g_xq8;
    } else {
        int sel = blockIdx.y;
        x = (sel == 0) ? xq : (sel == 1) ? xk : xv;
        sptr = (sel == 0) ? g_sq : (sel == 1) ? g_sk : g_sv;
        outq = (sel == 0) ? g_aq : (sel == 1) ? g_ak : g_av;
    }
    int tid = threadIdx.x;
    float m = 0.0f;
    for (int idx = tid; idx < B_ * D_; idx += 256) {
        int b = idx >> 9;          // D_ = 512
        int d = idx & (D_ - 1);
        m = fmaxf(m, fabsf(x[(b * T_ + t) * D_ + d]));
    }
    __shared__ float red[256];
    __shared__ float s_sh;
    red[tid] = m;
    __syncthreads();
    for (int s2 = 128; s2 > 0; s2 >>= 1) {
        if (tid < s2) red[tid] = fmaxf(red[tid], red[tid + s2]);
        __syncthreads();
    }
    if (tid == 0) { s_sh = make_scale(red[0]); sptr[t] = s_sh; }
    __syncthreads();
    float s = s_sh;
    for (int idx = tid; idx < B_ * D_; idx += 256) {
        int b = idx >> 9;
        int d = idx & (D_ - 1);
        int off = (b * T_ + t) * D_ + d;
        outq[off] = quant_val(x[off], s);
    }
}

// ---------------- weight quant: per-col scale, store int8 W^T -----------------
__global__ void weight_quant_kernel(const float* __restrict__ Wq,
                                    const float* __restrict__ Wk,
                                    const float* __restrict__ Wv) {
    int sel = blockIdx.y;
    const float* W = (sel == 0) ? Wq : (sel == 1) ? Wk : Wv;
    signed char* WT = (sel == 0) ? g_wtq : (sel == 1) ? g_wtk : g_wtv;
    float* WS = (sel == 0) ? g_wsq : (sel == 1) ? g_wsk : g_wsv;

    int j0 = blockIdx.x * 64;
    int tid = threadIdx.x;
    int tx = tid & 63;
    int ty = tid >> 6;  // 0..3

    float m = 0.0f;
    for (int i = ty; i < D_; i += 4)
        m = fmaxf(m, fabsf(W[i * D_ + j0 + tx]));

    __shared__ float red[4][64];
    __shared__ float sc[64];
    __shared__ signed char tile[64][68];  // [j][m] transposed stage
    red[ty][tx] = m;
    __syncthreads();
    if (ty == 0) {
        float mm = fmaxf(fmaxf(red[0][tx], red[1][tx]), fmaxf(red[2][tx], red[3][tx]));
        sc[tx] = make_scale(mm);
        WS[j0 + tx] = sc[tx];
    }
    __syncthreads();

    for (int kb = 0; kb < D_ / 64; kb++) {
        for (int u = 0; u < 16; u++) {
            int idx = tid + u * 256;
            int mrow = idx >> 6;
            int j = idx & 63;
            float w = W[(kb * 64 + mrow) * D_ + j0 + j];
            tile[j][mrow] = quant_val(w, sc[j]);
        }
        __syncthreads();
        int j = tid >> 2;
        for (int u = 0; u < 4; u++) {
            int mw = (tid & 3) + u * 4;
            unsigned int v = ((unsigned char)tile[j][mw * 4 + 0]) |
                             ((unsigned int)(unsigned char)tile[j][mw * 4 + 1] << 8) |
                             ((unsigned int)(unsigned char)tile[j][mw * 4 + 2] << 16) |
                             ((unsigned int)(unsigned char)tile[j][mw * 4 + 3] << 24);
            ((unsigned int*)WT)[(j0 + j) * (D_ / 4) + kb * 16 + mw] = v;
        }
        __syncthreads();
    }
}

// ---------------- projection GEMM: int8 dp4a, exact int32 accumulate ----------
__global__ void proj_gemm_i8_kernel() {
    int z = blockIdx.z;
    const signed char* A = (z == 0) ? g_aq : (z == 1) ? g_ak : g_av;
    const signed char* WT = (z == 0) ? g_wtq : (z == 1) ? g_wtk : g_wtv;
    const float* sA = (z == 0) ? g_sq : (z == 1) ? g_sk : g_sv;
    const float* sW = (z == 0) ? g_wsq : (z == 1) ? g_wsk : g_wsv;
    float* OUT = (z == 0) ? g_q : (z == 1) ? g_kk : g_vv;

    int row0 = blockIdx.y * 64;
    int col0 = blockIdx.x * 64;
    int tid = threadIdx.x;
    int tx = tid & 15;
    int ty = tid >> 4;

    __shared__ int As[64 * 17];
    __shared__ int Bs[64 * 17];

    int acc[4][4];
#pragma unroll
    for (int i = 0; i < 4; i++)
#pragma unroll
        for (int j = 0; j < 4; j++) acc[i][j] = 0;

    const int* Ai = (const int*)A;
    const int* Bi = (const int*)WT;
    int m = tid >> 2;
    int g = tid & 3;

    for (int kb = 0; kb < D_ / 64; kb++) {
        int4 av = *(const int4*)(&Ai[(row0 + m) * (D_ / 4) + kb * 16 + g * 4]);
        int4 bv = *(const int4*)(&Bi[(col0 + m) * (D_ / 4) + kb * 16 + g * 4]);
        As[m * 17 + g * 4 + 0] = av.x;
        As[m * 17 + g * 4 + 1] = av.y;
        As[m * 17 + g * 4 + 2] = av.z;
        As[m * 17 + g * 4 + 3] = av.w;
        Bs[m * 17 + g * 4 + 0] = bv.x;
        Bs[m * 17 + g * 4 + 1] = bv.y;
        Bs[m * 17 + g * 4 + 2] = bv.z;
        Bs[m * 17 + g * 4 + 3] = bv.w;
        __syncthreads();
#pragma unroll
        for (int kk = 0; kk < 16; kk++) {
            int a4[4], b4[4];
#pragma unroll
            for (int i = 0; i < 4; i++) a4[i] = As[(ty * 4 + i) * 17 + kk];
#pragma unroll
            for (int j = 0; j < 4; j++) b4[j] = Bs[(tx * 4 + j) * 17 + kk];
#pragma unroll
            for (int i = 0; i < 4; i++)
#pragma unroll
                for (int j = 0; j < 4; j++) acc[i][j] = __dp4a(a4[i], b4[j], acc[i][j]);
        }
        __syncthreads();
    }

    int h = col0 >> 6;  // 64-col tile == one head
#pragma unroll
    for (int i = 0; i < 4; i++) {
        int r = row0 + ty * 4 + i;
        int b = r >> 11;          // T_ = 2048
        int t = r & (T_ - 1);
        float st = sA[t];
        float4 v;
        v.x = (float)acc[i][0] * (st * sW[col0 + tx * 4 + 0]);
        v.y = (float)acc[i][1] * (st * sW[col0 + tx * 4 + 1]);
        v.z = (float)acc[i][2] * (st * sW[col0 + tx * 4 + 2]);
        v.w = (float)acc[i][3] * (st * sW[col0 + tx * 4 + 3]);
        *(float4*)(&OUT[((b * H_ + h) * T_ + t) * DK_ + tx * 4]) = v;
    }
}

// ---------------- K transpose: g_kk [bh][t][d] -> g_kkT [bh][d][t] ------------
__global__ void transpose_k_kernel() {
    __shared__ float tile[64 * 68];
    int bh = blockIdx.y;
    int t0 = blockIdx.x * 64;
    const float* K = g_kk + bh * T_ * DK_;
    int tid = threadIdx.x;
#pragma unroll
    for (int u = 0; u < 4; u++) {
        int f = tid + u * 256;
        int tt = f >> 4;       // 0..63 token row
        int dq = f & 15;       // float4 group in d
        float4 v = *(const float4*)(&K[(t0 + tt) * DK_ + dq * 4]);
        int pc = dq ^ (tt & 15);   // xor swizzle on 16B columns
        *(float4*)(&tile[tt * 68 + pc * 4]) = v;
    }
    __syncthreads();
#pragma unroll
    for (int u = 0; u < 4; u++) {
        int f = tid + u * 256;
        int d = f >> 4;        // 0..63 dim row
        int tq = f & 15;       // float4 group in t
        float4 v;
#pragma unroll
        for (int e = 0; e < 4; e++) {
            int row = tq * 4 + e;
            int pc = (d >> 2) ^ (row & 15);
            ((float*)&v)[e] = tile[row * 68 + pc * 4 + (d & 3)];
        }
        *(float4*)(&g_kkT[(bh * DK_ + d) * T_ + t0 + tq * 4]) = v;
    }
}

// ---------------- single-pass flash attention: FFMA2, BM=128, 8x8/thread ------
// 128 threads: tx = tid&7 (cols tx*8..+7), ty = tid>>3 (0..15).
// Thread rows: ty + 16*i, i=0..7  -> warp's 4 ty are CONSECUTIVE rows
// (stride-68 smem => conflict-free row-broadcast loads).
// Smem: Qs[128][68], PK[128][68] (Kt[64][68] aliased w/ P[q][68]), Vs[64][64].
#define ATT_SMEM ((128 * 68 + 128 * 68 + 64 * 64) * 4)

__global__ void __launch_bounds__(128) attention_kernel() {
    extern __shared__ float sm[];
    float* Qs = sm;                        // [row][d]   stride 68
    float* PK = sm + 128 * 68;             // Kt[d][kv] / Ps[q][kv], stride 68
    float* Vs = sm + 128 * 68 + 128 * 68;  // [kv][d]    stride 64

    int bh = blockIdx.y;
    int q0 = blockIdx.x * 128;
    const float* Q = g_q + bh * T_ * DK_;
    const float* KT = g_kkT + bh * DK_ * T_;
    const float* V = g_vv + bh * T_ * DK_;

    int tid = threadIdx.x;
    int tx = tid & 7;
    int ty = tid >> 3;

    // load Q tile [row][d], stride 68
#pragma unroll
    for (int u = 0; u < 16; u++) {
        int f = tid + u * 128;
        int m = f >> 4;
        int g = f & 15;
        *(float4*)(&Qs[m * 68 + g * 4]) =
            *(const float4*)(&Q[(q0 + m) * DK_ + g * 4]);
    }

    float mrow[8], lrow[8];
    ull Ov2[8][4];
#pragma unroll
    for (int i = 0; i < 8; i++) {
        mrow[i] = -1e30f;
        lrow[i] = 0.0f;
#pragma unroll
        for (int e = 0; e < 4; e++) Ov2[i][e] = 0ull;
    }

    for (int kt = 0; kt < T_ / 64; kt++) {
        __syncthreads();  // prior P/V reads done; Qs visible on iter 0
        // Kt tile rows d (stride 68), V natural rows kv (stride 64)
#pragma unroll
        for (int u = 0; u < 8; u++) {
            int f = tid + u * 128;
            int r = f >> 4;
            int g = f & 15;
            *(float4*)(&PK[r * 68 + g * 4]) =
                *(const float4*)(&KT[r * T_ + kt * 64 + g * 4]);
            *(float4*)(&Vs[r * 64 + g * 4]) =
                *(const float4*)(&V[(kt * 64 + r) * DK_ + g * 4]);
        }
        __syncthreads();

        // S = Q K^T : s2[i][0..3] = 4 f32x2 pairs over cols tx*8..+7
        ull s2[8][4];
#pragma unroll
        for (int i = 0; i < 8; i++)
#pragma unroll
            for (int e = 0; e < 4; e++) s2[i][e] = 0ull;

#pragma unroll 2
        for (int d4 = 0; d4 < 16; d4++) {
            ulonglong2 kfa[4], kfb[4];
#pragma unroll
            for (int e = 0; e < 4; e++) {
                kfa[e] = *(const ulonglong2*)(&PK[(d4 * 4 + e) * 68 + tx * 8]);
                kfb[e] = *(const ulonglong2*)(&PK[(d4 * 4 + e) * 68 + tx * 8 + 4]);
            }
#pragma unroll
            for (int i = 0; i < 8; i++) {
                float4 qv = *(const float4*)(&Qs[(ty + 16 * i) * 68 + d4 * 4]);
                ull a;
                a = dup2(qv.x);
                s2[i][0] = fma2(a, kfa[0].x, s2[i][0]);
                s2[i][1] = fma2(a, kfa[0].y, s2[i][1]);
                s2[i][2] = fma2(a, kfb[0].x, s2[i][2]);
                s2[i][3] = fma2(a, kfb[0].y, s2[i][3]);
                a = dup2(qv.y);
                s2[i][0] = fma2(a, kfa[1].x, s2[i][0]);
                s2[i][1] = fma2(a, kfa[1].y, s2[i][1]);
                s2[i][2] = fma2(a, kfb[1].x, s2[i][2]);
                s2[i][3] = fma2(a, kfb[1].y, s2[i][3]);
                a = dup2(qv.z);
                s2[i][0] = fma2(a, kfa[2].x, s2[i][0]);
                s2[i][1] = fma2(a, kfa[2].y, s2[i][1]);
                s2[i][2] = fma2(a, kfb[2].x, s2[i][2]);
                s2[i][3] = fma2(a, kfb[2].y, s2[i][3]);
                a = dup2(qv.w);
                s2[i][0] = fma2(a, kfa[3].x, s2[i][0]);
                s2[i][1] = fma2(a, kfa[3].y, s2[i][1]);
                s2[i][2] = fma2(a, kfb[3].x, s2[i][2]);
                s2[i][3] = fma2(a, kfb[3].y, s2[i][3]);
            }
        }
        __syncthreads();  // all Kt reads done; safe to overwrite with Ps

        // online softmax update + P tile store (s*0.125f: continuous op,
        // XLA strength-reduces /8 to *0.125 anyway; only quant divs are binned)
#pragma unroll
        for (int i = 0; i < 8; i++) {
            float2 f0 = unpk(s2[i][0]);
            float2 f1 = unpk(s2[i][1]);
            float2 f2 = unpk(s2[i][2]);
            float2 f3 = unpk(s2[i][3]);
            float sv[8];
            sv[0] = f0.x * 0.125f; sv[1] = f0.y * 0.125f;
            sv[2] = f1.x * 0.125f; sv[3] = f1.y * 0.125f;
            sv[4] = f2.x * 0.125f; sv[5] = f2.y * 0.125f;
            sv[6] = f3.x * 0.125f; sv[7] = f3.y * 0.125f;
            float tm = sv[0];
#pragma unroll
            for (int j = 1; j < 8; j++) tm = fmaxf(tm, sv[j]);
#pragma unroll
            for (int off = 4; off > 0; off >>= 1)
                tm = fmaxf(tm, __shfl_xor_sync(0xFFFFFFFFu, tm, off, 8));
            float newm = fmaxf(mrow[i], tm);
            float alpha = __expf(mrow[i] - newm);
            float p[8];
            float rs = 0.0f;
#pragma unroll
            for (int j = 0; j < 8; j++) {
                p[j] = __expf(sv[j] - newm);
                rs += p[j];
            }
#pragma unroll
            for (int off = 4; off > 0; off >>= 1)
                rs += __shfl_xor_sync(0xFFFFFFFFu, rs, off, 8);
            lrow[i] = lrow[i] * alpha + rs;
            mrow[i] = newm;
            ull am = dup2(alpha);
#pragma unroll
            for (int e = 0; e < 4; e++) Ov2[i][e] = mul2(Ov2[i][e], am);
            int prow = (ty + 16 * i) * 68 + tx * 8;
            *(float4*)(&PK[prow])     = make_float4(p[0], p[1], p[2], p[3]);
            *(float4*)(&PK[prow + 4]) = make_float4(p[4], p[5], p[6], p[7]);
        }
        __syncthreads();

        // O += P V : Ov2[i][0..3] pairs over d = tx*8..+7
#pragma unroll 2
        for (int j4 = 0; j4 < 16; j4++) {
            ulonglong2 vra[4], vrb[4];
#pragma unroll
            for (int e = 0; e < 4; e++) {
                vra[e] = *(const ulonglong2*)(&Vs[(j4 * 4 + e) * 64 + tx * 8]);
                vrb[e] = *(const ulonglong2*)(&Vs[(j4 * 4 + e) * 64 + tx * 8 + 4]);
            }
#pragma unroll
            for (int i = 0; i < 8; i++) {
                float4 pv = *(const float4*)(&PK[(ty + 16 * i) * 68 + j4 * 4]);
                ull a;
                a = dup2(pv.x);
                Ov2[i][0] = fma2(a, vra[0].x, Ov2[i][0]);
                Ov2[i][1] = fma2(a, vra[0].y, Ov2[i][1]);
                Ov2[i][2] = fma2(a, vrb[0].x, Ov2[i][2]);
                Ov2[i][3] = fma2(a, vrb[0].y, Ov2[i][3]);
                a = dup2(pv.y);
                Ov2[i][0] = fma2(a, vra[1].x, Ov2[i][0]);
                Ov2[i][1] = fma2(a, vra[1].y, Ov2[i][1]);
                Ov2[i][2] = fma2(a, vrb[1].x, Ov2[i][2]);
                Ov2[i][3] = fma2(a, vrb[1].y, Ov2[i][3]);
                a = dup2(pv.z);
                Ov2[i][0] = fma2(a, vra[2].x, Ov2[i][0]);
                Ov2[i][1] = fma2(a, vra[2].y, Ov2[i][1]);
                Ov2[i][2] = fma2(a, vrb[2].x, Ov2[i][2]);
                Ov2[i][3] = fma2(a, vrb[2].y, Ov2[i][3]);
                a = dup2(pv.w);
                Ov2[i][0] = fma2(a, vra[3].x, Ov2[i][0]);
                Ov2[i][1] = fma2(a, vra[3].y, Ov2[i][1]);
                Ov2[i][2] = fma2(a, vrb[3].x, Ov2[i][2]);
                Ov2[i][3] = fma2(a, vrb[3].y, Ov2[i][3]);
            }
        }
    }

    int b = bh >> 3;   // H_ = 8
    int h = bh & 7;
#pragma unroll
    for (int i = 0; i < 8; i++) {
        int t = q0 + ty + 16 * i;
        float2 o0 = unpk(Ov2[i][0]);
        float2 o1 = unpk(Ov2[i][1]);
        float2 o2 = unpk(Ov2[i][2]);
        float2 o3 = unpk(Ov2[i][3]);
        float4 va, vb;
        va.x = div_full(o0.x, lrow[i]);
        va.y = div_full(o0.y, lrow[i]);
        va.z = div_full(o1.x, lrow[i]);
        va.w = div_full(o1.y, lrow[i]);
        vb.x = div_full(o2.x, lrow[i]);
        vb.y = div_full(o2.y, lrow[i]);
        vb.z = div_full(o3.x, lrow[i]);
        vb.w = div_full(o3.y, lrow[i]);
        float* dst = &g_x[(b * T_ + t) * D_ + h * DK_ + tx * 8];
        *(float4*)(dst) = va;
        *(float4*)(dst + 4) = vb;
    }
}

// ---------------- final GEMM: dequant(int8 x) @ Wf, FMA2 inner ----------------
__global__ void final_gemm_kernel(const float* __restrict__ Wf,
                                  float* __restrict__ out) {
    int row0 = blockIdx.y * 64;
    int col0 = blockIdx.x * 64;
    int tid = threadIdx.x;
    int tx = tid & 15;
    int ty = tid >> 4;

    __shared__ float As[16][68];
    __shared__ float Bs[16][64];

    ull acc2[4][2];
#pragma unroll
    for (int i = 0; i < 4; i++) { acc2[i][0] = 0ull; acc2[i][1] = 0ull; }

    int m = tid >> 2;
    int g = tid & 3;
    float sm_scale = g_sx[(row0 + m) & (T_ - 1)];

    for (int kb = 0; kb < D_ / 16; kb++) {
        int av = ((const int*)g_xq8)[(row0 + m) * (D_ / 4) + kb * 4 + g];
#pragma unroll
        for (int u = 0; u < 4; u++) {
            int q8 = (av << (24 - 8 * u)) >> 24;  // sign-extended byte u
            As[g * 4 + u][m] = (float)q8 * sm_scale;
        }
#pragma unroll
        for (int i = 0; i < 4; i++) {
            int idx = tid + i * 256;
            int k = idx >> 6;
            int n = idx & 63;
            Bs[k][n] = Wf[(kb * 16 + k) * D_ + col0 + n];
        }
        __syncthreads();
#pragma unroll
        for (int k = 0; k < 16; k++) {
            float4 a = *(const float4*)(&As[k][ty * 4]);
            ulonglong2 b2 = *(const ulonglong2*)(&Bs[k][tx * 4]);
            float avv[4] = {a.x, a.y, a.z, a.w};
#pragma unroll
            for (int i = 0; i < 4; i++) {
                ull ad = dup2(avv[i]);
                acc2[i][0] = fma2(ad, b2.x, acc2[i][0]);
                acc2[i][1] = fma2(ad, b2.y, acc2[i][1]);
            }
        }
        __syncthreads();
    }

#pragma unroll
    for (int i = 0; i < 4; i++) {
        int r = row0 + ty * 4 + i;
        float2 lo = unpk(acc2[i][0]);
        float2 hi = unpk(acc2[i][1]);
        float4 v = make_float4(lo.x, lo.y, hi.x, hi.y);
        *(float4*)(&out[r * D_ + col0 + tx * 4]) = v;
    }
}

// ------------------------------ launcher --------------------------------------
extern "C" void kernel_launch(void* const* d_in, const int* in_sizes, int n_in,
                              void* d_out, int out_size) {
    (void)in_sizes; (void)n_in; (void)out_size;
    const float* q  = (const float*)d_in[0];
    const float* k  = (const float*)d_in[1];
    const float* v  = (const float*)d_in[2];
    const float* Wq = (const float*)d_in[3];
    const float* Wk = (const float*)d_in[4];
    const float* Wv = (const float*)d_in[5];
    const float* Wf = (const float*)d_in[6];
    float* out = (float*)d_out;

    cudaFuncSetAttribute(attention_kernel,
                         cudaFuncAttributeMaxDynamicSharedMemorySize, ATT_SMEM);

    act_quant_kernel<<<dim3(T_, 3), 256>>>(q, k, v, 0);
    weight_quant_kernel<<<dim3(D_ / 64, 3), 256>>>(Wq, Wk, Wv);
    proj_gemm_i8_kernel<<<dim3(D_ / 64, BT_ / 64, 3), 256>>>();
    transpose_k_kernel<<<dim3(T_ / 64, B_ * H_), 256>>>();
    attention_kernel<<<dim3(T_ / 128, B_ * H_), 128, ATT_SMEM>>>();
    act_quant_kernel<<<dim3(T_, 1), 256>>>(q, k, v, 1);
    final_gemm_kernel<<<dim3(D_ / 64, BT_ / 64), 256>>>(Wf, out);
}

// round 13
// speedup vs baseline: 1.8032x; 1.8032x over previous
#include <cuda_runtime.h>
#include <math.h>

// Problem constants
#define B_  4
#define T_  2048
#define D_  512
#define H_  8
#define DK_ 64
#define BT_ (B_ * T_)

// ---------------- device scratch (no allocations allowed) ----------------
__device__ float g_sq[T_], g_sk[T_], g_sv[T_], g_sx[T_];       // per-token act scales
__device__ float g_wsq[D_], g_wsk[D_], g_wsv[D_];              // per-col weight scales
__device__ signed char g_aq[BT_ * D_], g_ak[BT_ * D_], g_av[BT_ * D_]; // int8 acts
__device__ signed char g_xq8[BT_ * D_];                         // int8 of attention out
__device__ signed char g_wtq[D_ * D_], g_wtk[D_ * D_], g_wtv[D_ * D_]; // int8 W^T [j][k]
__device__ float g_q[B_ * H_ * T_ * DK_];
__device__ float g_kk[B_ * H_ * T_ * DK_];
__device__ float g_kkT[B_ * H_ * DK_ * T_];   // K transposed: [bh][d][t]
__device__ float g_vv[B_ * H_ * T_ * DK_];
__device__ float g_x[BT_ * D_];

// ---- emulate XLA:GPU's f32 division (div.full.f32, <=2ulp) — ONLY for the
// bit-critical quantization divisions (rintf bin boundaries) + final e/l. ----
__device__ __forceinline__ float div_full(float a, float b) {
    float r;
    asm("div.full.f32 %0, %1, %2;" : "=f"(r) : "f"(a), "f"(b));
    return r;
}
__device__ __forceinline__ float make_scale(float absmax) {
    return fmaxf(div_full(absmax, 127.0f), 1e-8f);
}
__device__ __forceinline__ signed char quant_val(float v, float s) {
    float q = rintf(div_full(v, s));
    q = fminf(127.0f, fmaxf(-128.0f, q));
    return (signed char)(int)q;
}

// ---- packed f32x2 helpers (Blackwell) — each lane an independent fp32 acc ----
typedef unsigned long long ull;
__device__ __forceinline__ ull fma2(ull a, ull b, ull c) {
    ull d;
    asm("fma.rn.f32x2 %0, %1, %2, %3;" : "=l"(d) : "l"(a), "l"(b), "l"(c));
    return d;
}
__device__ __forceinline__ ull mul2(ull a, ull b) {
    ull d;
    asm("mul.rn.f32x2 %0, %1, %2;" : "=l"(d) : "l"(a), "l"(b));
    return d;
}
__device__ __forceinline__ ull dup2(float x) {
    ull d;
    asm("mov.b64 %0, {%1, %1};" : "=l"(d) : "f"(x));
    return d;
}
__device__ __forceinline__ float2 unpk(ull v) {
    float lo, hi;
    asm("mov.b64 {%0, %1}, %2;" : "=f"(lo), "=f"(hi) : "l"(v));
    return make_float2(lo, hi);
}

// ---------------- per-token activation scale + int8 quantize ------------------
__global__ void act_quant_kernel(const float* __restrict__ xq,
                                 const float* __restrict__ xk,
                                 const float* __restrict__ xv,
                                 int final_mode) {
    int t = blockIdx.x;
    const float* x;
    float* sptr;
    signed char* outq;
    if (final_mode) {
        x = g_x; sptr = g_sx; outq = g_xq8;
    } else {
        int sel = blockIdx.y;
        x = (sel == 0) ? xq : (sel == 1) ? xk : xv;
        sptr = (sel == 0) ? g_sq : (sel == 1) ? g_sk : g_sv;
        outq = (sel == 0) ? g_aq : (sel == 1) ? g_ak : g_av;
    }
    int tid = threadIdx.x;
    float m = 0.0f;
    for (int idx = tid; idx < B_ * D_; idx += 256) {
        int b = idx >> 9;          // D_ = 512
        int d = idx & (D_ - 1);
        m = fmaxf(m, fabsf(x[(b * T_ + t) * D_ + d]));
    }
    __shared__ float red[256];
    __shared__ float s_sh;
    red[tid] = m;
    __syncthreads();
    for (int s2 = 128; s2 > 0; s2 >>= 1) {
        if (tid < s2) red[tid] = fmaxf(red[tid], red[tid + s2]);
        __syncthreads();
    }
    if (tid == 0) { s_sh = make_scale(red[0]); sptr[t] = s_sh; }
    __syncthreads();
    float s = s_sh;
    for (int idx = tid; idx < B_ * D_; idx += 256) {
        int b = idx >> 9;
        int d = idx & (D_ - 1);
        int off = (b * T_ + t) * D_ + d;
        outq[off] = quant_val(x[off], s);
    }
}

// ---------------- weight quant: per-col scale, store int8 W^T -----------------
__global__ void weight_quant_kernel(const float* __restrict__ Wq,
                                    const float* __restrict__ Wk,
                                    const float* __restrict__ Wv) {
    int sel = blockIdx.y;
    const float* W = (sel == 0) ? Wq : (sel == 1) ? Wk : Wv;
    signed char* WT = (sel == 0) ? g_wtq : (sel == 1) ? g_wtk : g_wtv;
    float* WS = (sel == 0) ? g_wsq : (sel == 1) ? g_wsk : g_wsv;

    int j0 = blockIdx.x * 64;
    int tid = threadIdx.x;
    int tx = tid & 63;
    int ty = tid >> 6;  // 0..3

    float m = 0.0f;
    for (int i = ty; i < D_; i += 4)
        m = fmaxf(m, fabsf(W[i * D_ + j0 + tx]));

    __shared__ float red[4][64];
    __shared__ float sc[64];
    __shared__ signed char tile[64][68];  // [j][m] transposed stage
    red[ty][tx] = m;
    __syncthreads();
    if (ty == 0) {
        float mm = fmaxf(fmaxf(red[0][tx], red[1][tx]), fmaxf(red[2][tx], red[3][tx]));
        sc[tx] = make_scale(mm);
        WS[j0 + tx] = sc[tx];
    }
    __syncthreads();

    for (int kb = 0; kb < D_ / 64; kb++) {
        for (int u = 0; u < 16; u++) {
            int idx = tid + u * 256;
            int mrow = idx >> 6;
            int j = idx & 63;
            float w = W[(kb * 64 + mrow) * D_ + j0 + j];
            tile[j][mrow] = quant_val(w, sc[j]);
        }
        __syncthreads();
        int j = tid >> 2;
        for (int u = 0; u < 4; u++) {
            int mw = (tid & 3) + u * 4;
            unsigned int v = ((unsigned char)tile[j][mw * 4 + 0]) |
                             ((unsigned int)(unsigned char)tile[j][mw * 4 + 1] << 8) |
                             ((unsigned int)(unsigned char)tile[j][mw * 4 + 2] << 16) |
                             ((unsigned int)(unsigned char)tile[j][mw * 4 + 3] << 24);
            ((unsigned int*)WT)[(j0 + j) * (D_ / 4) + kb * 16 + mw] = v;
        }
        __syncthreads();
    }
}

// ---------------- projection GEMM: int8 dp4a, exact int32 accumulate ----------
__global__ void proj_gemm_i8_kernel() {
    int z = blockIdx.z;
    const signed char* A = (z == 0) ? g_aq : (z == 1) ? g_ak : g_av;
    const signed char* WT = (z == 0) ? g_wtq : (z == 1) ? g_wtk : g_wtv;
    const float* sA = (z == 0) ? g_sq : (z == 1) ? g_sk : g_sv;
    const float* sW = (z == 0) ? g_wsq : (z == 1) ? g_wsk : g_wsv;
    float* OUT = (z == 0) ? g_q : (z == 1) ? g_kk : g_vv;

    int row0 = blockIdx.y * 64;
    int col0 = blockIdx.x * 64;
    int tid = threadIdx.x;
    int tx = tid & 15;
    int ty = tid >> 4;

    __shared__ int As[64 * 17];
    __shared__ int Bs[64 * 17];

    int acc[4][4];
#pragma unroll
    for (int i = 0; i < 4; i++)
#pragma unroll
        for (int j = 0; j < 4; j++) acc[i][j] = 0;

    const int* Ai = (const int*)A;
    const int* Bi = (const int*)WT;
    int m = tid >> 2;
    int g = tid & 3;

    for (int kb = 0; kb < D_ / 64; kb++) {
        int4 av = *(const int4*)(&Ai[(row0 + m) * (D_ / 4) + kb * 16 + g * 4]);
        int4 bv = *(const int4*)(&Bi[(col0 + m) * (D_ / 4) + kb * 16 + g * 4]);
        As[m * 17 + g * 4 + 0] = av.x;
        As[m * 17 + g * 4 + 1] = av.y;
        As[m * 17 + g * 4 + 2] = av.z;
        As[m * 17 + g * 4 + 3] = av.w;
        Bs[m * 17 + g * 4 + 0] = bv.x;
        Bs[m * 17 + g * 4 + 1] = bv.y;
        Bs[m * 17 + g * 4 + 2] = bv.z;
        Bs[m * 17 + g * 4 + 3] = bv.w;
        __syncthreads();
#pragma unroll
        for (int kk = 0; kk < 16; kk++) {
            int a4[4], b4[4];
#pragma unroll
            for (int i = 0; i < 4; i++) a4[i] = As[(ty * 4 + i) * 17 + kk];
#pragma unroll
            for (int j = 0; j < 4; j++) b4[j] = Bs[(tx * 4 + j) * 17 + kk];
#pragma unroll
            for (int i = 0; i < 4; i++)
#pragma unroll
                for (int j = 0; j < 4; j++) acc[i][j] = __dp4a(a4[i], b4[j], acc[i][j]);
        }
        __syncthreads();
    }

    int h = col0 >> 6;  // 64-col tile == one head
#pragma unroll
    for (int i = 0; i < 4; i++) {
        int r = row0 + ty * 4 + i;
        int b = r >> 11;          // T_ = 2048
        int t = r & (T_ - 1);
        float st = sA[t];
        float4 v;
        v.x = (float)acc[i][0] * (st * sW[col0 + tx * 4 + 0]);
        v.y = (float)acc[i][1] * (st * sW[col0 + tx * 4 + 1]);
        v.z = (float)acc[i][2] * (st * sW[col0 + tx * 4 + 2]);
        v.w = (float)acc[i][3] * (st * sW[col0 + tx * 4 + 3]);
        *(float4*)(&OUT[((b * H_ + h) * T_ + t) * DK_ + tx * 4]) = v;
    }
}

// ---------------- K transpose: g_kk [bh][t][d] -> g_kkT [bh][d][t] ------------
__global__ void transpose_k_kernel() {
    __shared__ float tile[64 * 68];
    int bh = blockIdx.y;
    int t0 = blockIdx.x * 64;
    const float* K = g_kk + bh * T_ * DK_;
    int tid = threadIdx.x;
#pragma unroll
    for (int u = 0; u < 4; u++) {
        int f = tid + u * 256;
        int tt = f >> 4;       // 0..63 token row
        int dq = f & 15;       // float4 group in d
        float4 v = *(const float4*)(&K[(t0 + tt) * DK_ + dq * 4]);
        int pc = dq ^ (tt & 15);   // xor swizzle on 16B columns
        *(float4*)(&tile[tt * 68 + pc * 4]) = v;
    }
    __syncthreads();
#pragma unroll
    for (int u = 0; u < 4; u++) {
        int f = tid + u * 256;
        int d = f >> 4;        // 0..63 dim row
        int tq = f & 15;       // float4 group in t
        float4 v;
#pragma unroll
        for (int e = 0; e < 4; e++) {
            int row = tq * 4 + e;
            int pc = (d >> 2) ^ (row & 15);
            ((float*)&v)[e] = tile[row * 68 + pc * 4 + (d & 3)];
        }
        *(float4*)(&g_kkT[(bh * DK_ + d) * T_ + t0 + tq * 4]) = v;
    }
}

// ---------------- single-pass flash attention: FFMA2 + exp-gating -------------
// BM=BN=64, dk=64, 128 threads, thread tile 8 rows x 4 cols (R7 layout).
// Exp-gating: if a row's tile-max is >30 below its running max, every exp
// underflows below 1e-13 rel — store zero P row, skip exps.
// CRITICAL: shuffles inside the gated branch use the 16-lane SEGMENT mask
// (gate is uniform per segment, but the two segments of a warp may diverge).
#define ATT_SMEM ((64 * 64 + 64 * 68 + 64 * 64) * 4)

__global__ void __launch_bounds__(128, 4) attention_kernel() {
    extern __shared__ float sm[];
    float* Qs = sm;                      // [row][d]   stride 64
    float* PK = sm + 64 * 64;            // Kt[d][kv] / Ps[q][kv], stride 68
    float* Vs = sm + 64 * 64 + 64 * 68;  // [kv][d]    stride 64

    int bh = blockIdx.y;
    int q0 = blockIdx.x * 64;
    const float* Q = g_q + bh * T_ * DK_;
    const float* KT = g_kkT + bh * DK_ * T_;
    const float* V = g_vv + bh * T_ * DK_;

    int tid = threadIdx.x;
    int tx = tid & 15;
    int ty = tid >> 4;
    unsigned smask = 0xFFFFu << (tid & 16);   // this thread's 16-lane segment

    // load Q tile [row][d]
#pragma unroll
    for (int u = 0; u < 8; u++) {
        int f = tid + u * 128;
        int m = f >> 4;
        int dq = f & 15;
        *(float4*)(&Qs[m * 64 + dq * 4]) =
            *(const float4*)(&Q[(q0 + m) * DK_ + dq * 4]);
    }

    float mrow[8], lrow[8];
    ull Ov2[8][2];
#pragma unroll
    for (int i = 0; i < 8; i++) {
        mrow[i] = -1e30f;
        lrow[i] = 0.0f;
        Ov2[i][0] = 0ull;
        Ov2[i][1] = 0ull;
    }

    for (int kt = 0; kt < T_ / 64; kt++) {
        __syncthreads();  // prior P/V reads done; Qs visible on iter 0
#pragma unroll
        for (int u = 0; u < 8; u++) {
            int f = tid + u * 128;
            int r = f >> 4;          // d for Kt / kv for Vs
            int c = f & 15;          // float4 group
            *(float4*)(&PK[r * 68 + c * 4]) =
                *(const float4*)(&KT[r * T_ + kt * 64 + c * 4]);
            *(float4*)(&Vs[r * 64 + c * 4]) =
                *(const float4*)(&V[(kt * 64 + r) * DK_ + c * 4]);
        }
        __syncthreads();

        // S = Q K^T : s2[i] = two f32x2 pairs over cols (tx*4 .. tx*4+3)
        ull s2[8][2];
#pragma unroll
        for (int i = 0; i < 8; i++) { s2[i][0] = 0ull; s2[i][1] = 0ull; }

#pragma unroll 2
        for (int d4 = 0; d4 < 16; d4++) {
            ulonglong2 kf0 = *(const ulonglong2*)(&PK[(d4 * 4 + 0) * 68 + tx * 4]);
            ulonglong2 kf1 = *(const ulonglong2*)(&PK[(d4 * 4 + 1) * 68 + tx * 4]);
            ulonglong2 kf2 = *(const ulonglong2*)(&PK[(d4 * 4 + 2) * 68 + tx * 4]);
            ulonglong2 kf3 = *(const ulonglong2*)(&PK[(d4 * 4 + 3) * 68 + tx * 4]);
#pragma unroll
            for (int i = 0; i < 8; i++) {
                float4 qv = *(const float4*)(&Qs[(ty * 8 + i) * 64 + d4 * 4]);
                ull ax = dup2(qv.x), ay = dup2(qv.y), az = dup2(qv.z), aw = dup2(qv.w);
                s2[i][0] = fma2(ax, kf0.x, s2[i][0]);
                s2[i][1] = fma2(ax, kf0.y, s2[i][1]);
                s2[i][0] = fma2(ay, kf1.x, s2[i][0]);
                s2[i][1] = fma2(ay, kf1.y, s2[i][1]);
                s2[i][0] = fma2(az, kf2.x, s2[i][0]);
                s2[i][1] = fma2(az, kf2.y, s2[i][1]);
                s2[i][0] = fma2(aw, kf3.x, s2[i][0]);
                s2[i][1] = fma2(aw, kf3.y, s2[i][1]);
            }
        }
        __syncthreads();  // all Kt reads done; safe to overwrite with Ps

        // online softmax with exp-gating (segment-masked shuffles)
#pragma unroll
        for (int i = 0; i < 8; i++) {
            float2 lo = unpk(s2[i][0]);
            float2 hi = unpk(s2[i][1]);
            float sv0 = lo.x * 0.125f;
            float sv1 = lo.y * 0.125f;
            float sv2 = hi.x * 0.125f;
            float sv3 = hi.y * 0.125f;
            float tm = fmaxf(fmaxf(sv0, sv1), fmaxf(sv2, sv3));
#pragma unroll
            for (int off = 8; off > 0; off >>= 1)
                tm = fmaxf(tm, __shfl_xor_sync(smask, tm, off, 16));
            // gate is uniform across the 16-lane segment (tm, mrow both uniform)
            if (tm - mrow[i] < -30.0f) {
                *(float4*)(&PK[(ty * 8 + i) * 68 + tx * 4]) =
                    make_float4(0.0f, 0.0f, 0.0f, 0.0f);
            } else {
                float newm = fmaxf(mrow[i], tm);
                float alpha = __expf(mrow[i] - newm);
                float p0 = __expf(sv0 - newm);
                float p1 = __expf(sv1 - newm);
                float p2 = __expf(sv2 - newm);
                float p3 = __expf(sv3 - newm);
                float rs = p0 + p1 + p2 + p3;
#pragma unroll
                for (int off = 8; off > 0; off >>= 1)
                    rs += __shfl_xor_sync(smask, rs, off, 16);
                lrow[i] = lrow[i] * alpha + rs;
                mrow[i] = newm;
                ull am = dup2(alpha);
                Ov2[i][0] = mul2(Ov2[i][0], am);
                Ov2[i][1] = mul2(Ov2[i][1], am);
                *(float4*)(&PK[(ty * 8 + i) * 68 + tx * 4]) =
                    make_float4(p0, p1, p2, p3);
            }
        }
        __syncthreads();

        // O += P V : Ov2[i] = two f32x2 pairs over d (tx*4 .. tx*4+3)
#pragma unroll 2
        for (int j4 = 0; j4 < 16; j4++) {
            ulonglong2 vr0 = *(const ulonglong2*)(&Vs[(j4 * 4 + 0) * 64 + tx * 4]);
            ulonglong2 vr1 = *(const ulonglong2*)(&Vs[(j4 * 4 + 1) * 64 + tx * 4]);
            ulonglong2 vr2 = *(const ulonglong2*)(&Vs[(j4 * 4 + 2) * 64 + tx * 4]);
            ulonglong2 vr3 = *(const ulonglong2*)(&Vs[(j4 * 4 + 3) * 64 + tx * 4]);
#pragma unroll
            for (int i = 0; i < 8; i++) {
                float4 pv = *(const float4*)(&PK[(ty * 8 + i) * 68 + j4 * 4]);
                ull ax = dup2(pv.x), ay = dup2(pv.y), az = dup2(pv.z), aw = dup2(pv.w);
                Ov2[i][0] = fma2(ax, vr0.x, Ov2[i][0]);
                Ov2[i][1] = fma2(ax, vr0.y, Ov2[i][1]);
                Ov2[i][0] = fma2(ay, vr1.x, Ov2[i][0]);
                Ov2[i][1] = fma2(ay, vr1.y, Ov2[i][1]);
                Ov2[i][0] = fma2(az, vr2.x, Ov2[i][0]);
                Ov2[i][1] = fma2(az, vr2.y, Ov2[i][1]);
                Ov2[i][0] = fma2(aw, vr3.x, Ov2[i][0]);
                Ov2[i][1] = fma2(aw, vr3.y, Ov2[i][1]);
            }
        }
    }

    int b = bh >> 3;   // H_ = 8
    int h = bh & 7;
#pragma unroll
    for (int i = 0; i < 8; i++) {
        int t = q0 + ty * 8 + i;
        float2 o01 = unpk(Ov2[i][0]);
        float2 o23 = unpk(Ov2[i][1]);
        float4 v;
        v.x = div_full(o01.x, lrow[i]);
        v.y = div_full(o01.y, lrow[i]);
        v.z = div_full(o23.x, lrow[i]);
        v.w = div_full(o23.y, lrow[i]);
        *(float4*)(&g_x[(b * T_ + t) * D_ + h * DK_ + tx * 4]) = v;
    }
}

// ---------------- final GEMM: dequant(int8 x) @ Wf, FMA2 inner ----------------
__global__ void final_gemm_kernel(const float* __restrict__ Wf,
                                  float* __restrict__ out) {
    int row0 = blockIdx.y * 64;
    int col0 = blockIdx.x * 64;
    int tid = threadIdx.x;
    int tx = tid & 15;
    int ty = tid >> 4;

    __shared__ float As[16][68];
    __shared__ float Bs[16][64];

    ull acc2[4][2];
#pragma unroll
    for (int i = 0; i < 4; i++) { acc2[i][0] = 0ull; acc2[i][1] = 0ull; }

    int m = tid >> 2;
    int g = tid & 3;
    float sm_scale = g_sx[(row0 + m) & (T_ - 1)];

    for (int kb = 0; kb < D_ / 16; kb++) {
        int av = ((const int*)g_xq8)[(row0 + m) * (D_ / 4) + kb * 4 + g];
#pragma unroll
        for (int u = 0; u < 4; u++) {
            int q8 = (av << (24 - 8 * u)) >> 24;  // sign-extended byte u
            As[g * 4 + u][m] = (float)q8 * sm_scale;
        }
#pragma unroll
        for (int i = 0; i < 4; i++) {
            int idx = tid + i * 256;
            int k = idx >> 6;
            int n = idx & 63;
            Bs[k][n] = Wf[(kb * 16 + k) * D_ + col0 + n];
        }
        __syncthreads();
#pragma unroll
        for (int k = 0; k < 16; k++) {
            float4 a = *(const float4*)(&As[k][ty * 4]);
            ulonglong2 b2 = *(const ulonglong2*)(&Bs[k][tx * 4]);
            float avv[4] = {a.x, a.y, a.z, a.w};
#pragma unroll
            for (int i = 0; i < 4; i++) {
                ull ad = dup2(avv[i]);
                acc2[i][0] = fma2(ad, b2.x, acc2[i][0]);
                acc2[i][1] = fma2(ad, b2.y, acc2[i][1]);
            }
        }
        __syncthreads();
    }

#pragma unroll
    for (int i = 0; i < 4; i++) {
        int r = row0 + ty * 4 + i;
        float2 lo = unpk(acc2[i][0]);
        float2 hi = unpk(acc2[i][1]);
        float4 v = make_float4(lo.x, lo.y, hi.x, hi.y);
        *(float4*)(&out[r * D_ + col0 + tx * 4]) = v;
    }
}

// ------------------------------ launcher --------------------------------------
extern "C" void kernel_launch(void* const* d_in, const int* in_sizes, int n_in,
                              void* d_out, int out_size) {
    (void)in_sizes; (void)n_in; (void)out_size;
    const float* q  = (const float*)d_in[0];
    const float* k  = (const float*)d_in[1];
    const float* v  = (const float*)d_in[2];
    const float* Wq = (const float*)d_in[3];
    const float* Wk = (const float*)d_in[4];
    const float* Wv = (const float*)d_in[5];
    const float* Wf = (const float*)d_in[6];
    float* out = (float*)d_out;

    cudaFuncSetAttribute(attention_kernel,
                         cudaFuncAttributeMaxDynamicSharedMemorySize, ATT_SMEM);

    act_quant_kernel<<<dim3(T_, 3), 256>>>(q, k, v, 0);
    weight_quant_kernel<<<dim3(D_ / 64, 3), 256>>>(Wq, Wk, Wv);
    proj_gemm_i8_kernel<<<dim3(D_ / 64, BT_ / 64, 3), 256>>>();
    transpose_k_kernel<<<dim3(T_ / 64, B_ * H_), 256>>>();
    attention_kernel<<<dim3(T_ / 64, B_ * H_), 128, ATT_SMEM>>>();
    act_quant_kernel<<<dim3(T_, 1), 256>>>(q, k, v, 1);
    final_gemm_kernel<<<dim3(D_ / 64, BT_ / 64), 256>>>(Wf, out);
}